// round 16
// baseline (speedup 1.0000x reference)
#include <cuda_runtime.h>
#include <cstdint>

#define TT 2048
#define BB 128
#define HH 200
#define KS 20     // k-span per chunk (10 chunks x 20 = 200)
#define NKC 10    // k-chunks
#define NJO 25    // j-octets (8 j each): 25*8 = 200
// compute threads: tid = kc*25 + jo, 250 total; block 256 (8 warps)
// phase B: tid<200 reduce+tanh; warp 7 does the output head

typedef unsigned long long ull;

__device__ __forceinline__ void fma2(ull& acc, ull a, ull b) {
    asm("fma.rn.f32x2 %0, %1, %2, %0;" : "+l"(acc) : "l"(a), "l"(b));
}
__device__ __forceinline__ void unpack2(ull v, float& lo, float& hi) {
    asm("mov.b64 {%0,%1}, %2;" : "=f"(lo), "=f"(hi) : "l"(v));
}
__device__ __forceinline__ float tanh_hw(float x) {
    float r; asm("tanh.approx.f32 %0, %1;" : "=f"(r) : "f"(x));
    return r;
}

__global__ void __launch_bounds__(256, 1) rnn_kernel(
    const float* __restrict__ x,     // [T, B, 2]
    const float* __restrict__ Wih,   // [H, 2]
    const float* __restrict__ Whh,   // [H, H]
    const float* __restrict__ bih,   // [H]
    const float* __restrict__ bhh,   // [H]
    const float* __restrict__ Wout,  // [1, H]
    const float* __restrict__ bOut,  // [1]
    float* __restrict__ out)         // [T, B, 1]
{
    __shared__ __align__(16) float2 xsm[TT];          // 16 KB input sequence
    __shared__ __align__(16) float  hsm[2][HH];       // double-buffered hidden
    __shared__ __align__(16) float  part[NKC * HH];   // partials [kc*200 + j]
    __shared__ __align__(16) float  wosm[HH];         // Wout staged

    const int tid = threadIdx.x;
    const int b   = blockIdx.x;
    const int kc  = tid / NJO;        // 0..9 for compute threads
    const int jo  = tid - kc * NJO;   // 0..24
    const bool compute = (tid < 250);
    const int lane = tid & 31;
    const bool headw = (tid >= 224);  // warp 7 (head duty in phase B)

    // Preload input sequence for this batch
    for (int i = tid; i < TT; i += 256)
        xsm[i] = *(const float2*)(x + ((size_t)i * BB + b) * 2);
    if (tid < HH) wosm[tid] = Wout[tid];

    // W registers: 8 rows (j = 8jo+r), k-chunk [20kc, +20) as 10 u64 each.
    // 80 regs of W; each h-quad (LDS.128) is reused 8x.
    ull wr[8][10];
    if (compute) {
#pragma unroll
        for (int r = 0; r < 8; r++) {
            const ull* wrow = (const ull*)(Whh + (size_t)(8 * jo + r) * HH + KS * kc);
#pragma unroll
            for (int i = 0; i < 10; i++) wr[r][i] = wrow[i];
        }
    }

    // Epilogue constants (threads 0..199, keyed by j = tid)
    float wih0 = 0.f, wih1 = 0.f, bias = 0.f;
    if (tid < HH) {
        wih0 = Wih[2 * tid];
        wih1 = Wih[2 * tid + 1];
        bias = bih[tid] + bhh[tid];
    }
    const float bo = bOut[0];

    // h_0 = 0 in both buffers
    if (tid < 2 * HH) ((float*)hsm)[tid] = 0.0f;
    __syncthreads();

    // iter t: hsm[rp] = h_{t-1}; phase B writes hs[t] into hsm[rp^1];
    // warp 7 emits out[t-1] = head(h_{t-1}) during phase B.
    auto step = [&](int t, int rp) {
        // ---- Phase A: 8-row x 20-k partials
        if (compute) {
            const ulonglong2* hp = (const ulonglong2*)(&hsm[rp][KS * kc]); // 80B, 16B-aligned
            ull a[8] = {0ull, 0ull, 0ull, 0ull, 0ull, 0ull, 0ull, 0ull};
#pragma unroll
            for (int i = 0; i < 5; i++) {
                ulonglong2 hv = hp[i];             // one LDS.128, reused 8x
#pragma unroll
                for (int r = 0; r < 8; r++) {
                    fma2(a[r], hv.x, wr[r][2 * i]);
                    fma2(a[r], hv.y, wr[r][2 * i + 1]);
                }
            }
            float4 p0, p1;
            { float lo, hi; unpack2(a[0], lo, hi); p0.x = lo + hi; }
            { float lo, hi; unpack2(a[1], lo, hi); p0.y = lo + hi; }
            { float lo, hi; unpack2(a[2], lo, hi); p0.z = lo + hi; }
            { float lo, hi; unpack2(a[3], lo, hi); p0.w = lo + hi; }
            { float lo, hi; unpack2(a[4], lo, hi); p1.x = lo + hi; }
            { float lo, hi; unpack2(a[5], lo, hi); p1.y = lo + hi; }
            { float lo, hi; unpack2(a[6], lo, hi); p1.z = lo + hi; }
            { float lo, hi; unpack2(a[7], lo, hi); p1.w = lo + hi; }
            float* dst = &part[NKC == 0 ? 0 : (200 * kc + 8 * jo)];
            *(float4*)(dst)     = p0;             // 16B-aligned (8jo, 200kc even)
            *(float4*)(dst + 4) = p1;
        }
        __syncthreads();

        // ---- Phase B: reduce 10 k-chunks + tanh + publish (tid<200);
        //               warp 7: head(h_{t-1}) -> out[t-1]
        if (tid < HH) {
            float s = 0.0f;
#pragma unroll
            for (int c = 0; c < NKC; c++) s += part[200 * c + tid];
            float2 xv = xsm[t];
            float pre = fmaf(xv.x, wih0, fmaf(xv.y, wih1, s + bias));
            hsm[rp ^ 1][tid] = tanh_hw(pre);
        } else if (headw && t > 0) {
            const float* hv = hsm[rp];
            float acc = 0.0f;
#pragma unroll
            for (int i = 0; i < 7; i++) {
                int idx = lane + 32 * i;
                if (idx < HH) acc = fmaf(hv[idx], wosm[idx], acc);
            }
#pragma unroll
            for (int off = 16; off; off >>= 1)
                acc += __shfl_xor_sync(0xFFFFFFFFu, acc, off);
            if (lane == 0) out[(size_t)(t - 1) * BB + b] = acc + bo;
        }
        __syncthreads();
    };

#pragma unroll 1
    for (int t = 0; t < TT; t += 2) {
        step(t, 0);
        step(t + 1, 1);
    }

    // Final output: hs[TT-1] ended in hsm[0]
    if (headw) {
        const float* hv = hsm[0];
        float acc = 0.0f;
#pragma unroll
        for (int i = 0; i < 7; i++) {
            int idx = lane + 32 * i;
            if (idx < HH) acc = fmaf(hv[idx], wosm[idx], acc);
        }
#pragma unroll
        for (int off = 16; off; off >>= 1)
            acc += __shfl_xor_sync(0xFFFFFFFFu, acc, off);
        if (lane == 0) out[(size_t)(TT - 1) * BB + b] = acc + bo;
    }
}

extern "C" void kernel_launch(void* const* d_in, const int* in_sizes, int n_in,
                              void* d_out, int out_size) {
    const float* input_seq = (const float*)d_in[0];  // [T,B,2]
    const float* W_ih      = (const float*)d_in[1];  // [H,2]
    const float* W_hh      = (const float*)d_in[2];  // [H,H]
    const float* b_ih      = (const float*)d_in[3];  // [H]
    const float* b_hh      = (const float*)d_in[4];  // [H]
    const float* W_out     = (const float*)d_in[5];  // [1,H]
    const float* b_out     = (const float*)d_in[6];  // [1]
    float* out = (float*)d_out;                      // [T,B,1]

    rnn_kernel<<<BB, 256>>>(input_seq, W_ih, W_hh, b_ih, b_hh, W_out, b_out, out);
}